// round 15
// baseline (speedup 1.0000x reference)
#include <cuda_runtime.h>

// Problem constants (fixed by the dataset): N=200000, E=6400000, F: 128 -> 8 -> 16
#define NMAX 200000
#define EMAX 6400000

// Scratch (no cudaMalloc allowed)
__device__ float g_deg[NMAX];         // degree (float counts)
__device__ float g_dis[NMAX];         // deg^-1/2
__device__ float g_h[NMAX * 8];       // (x @ W1) * dis[src]   (pre-scaled)
__device__ float g_agg[NMAX * 8];     // layer-1 unweighted aggregation
__device__ float g_r[NMAX * 8];       // relu(...) * dis[src]  (pre-scaled)
__device__ float g_agg2[NMAX * 8];    // layer-2 unweighted aggregation
__device__ int   g_is64;              // edge_index dtype flag

// ---------------------------------------------------------------------------
// K0: deg init + dtype detect (thread 0 of block 0).
__global__ void k_init(const void* ei, int N) {
    int i = blockIdx.x * blockDim.x + threadIdx.x;
    if (i < N) g_deg[i] = 1.0f;   // self-loop
    if (i == 0) {
        const long long* p = (const long long*)ei;
        int is64 = 1;
#pragma unroll
        for (int k = 0; k < 8; k++) {
            long long v = p[k];
            if (v < 0 || v >= (long long)N) is64 = 0;
        }
        g_is64 = is64;
    }
}

// ---------------------------------------------------------------------------
// K1: degree scatter only — streams the dst half of edge_index, 8 edges/thread.
__global__ void k_deg(const void* ei, int E) {
    int t = blockIdx.x * blockDim.x + threadIdx.x;
    int e = t * 8;
    if (e >= E) return;
    int d[8];
    int cnt = (E - e < 8) ? (E - e) : 8;
    if (g_is64) {
        const long long* p = (const long long*)ei + E + e;
        if (cnt == 8) {
#pragma unroll
            for (int q = 0; q < 4; q++) {
                longlong2 v = *(const longlong2*)(p + q * 2);
                d[q * 2] = (int)v.x; d[q * 2 + 1] = (int)v.y;
            }
        } else {
            for (int q = 0; q < cnt; q++) d[q] = (int)p[q];
        }
    } else {
        const int* p = (const int*)ei + E + e;
        if (cnt == 8) {
            int4 a = *(const int4*)p, b = *(const int4*)(p + 4);
            d[0] = a.x; d[1] = a.y; d[2] = a.z; d[3] = a.w;
            d[4] = b.x; d[5] = b.y; d[6] = b.z; d[7] = b.w;
        } else {
            for (int q = 0; q < cnt; q++) d[q] = p[q];
        }
    }
    for (int q = 0; q < cnt; q++) atomicAdd(&g_deg[d[q]], 1.0f);
}

// ---------------------------------------------------------------------------
// K2: h_scaled = (x @ W1) * dis. Warp per 2 nodes, grid-stride. W in regs.
// Fused: dis = rsqrt(deg) stored once, agg init = h_scaled (self-loop term).
// __launch_bounds__(256, 5): cap regs ~51 so 5 blocks/SM (62.5% occ) for MLP.
__global__ void __launch_bounds__(256, 5)
k_gemm1(const float* __restrict__ x, const float* __restrict__ W1, int N) {
    int lane = threadIdx.x & 31;
    int cg   = lane >> 2;
    int fp   = lane & 3;

    float2 w2[16];
#pragma unroll
    for (int c = 0; c < 16; c++)
        w2[c] = *(const float2*)&W1[(cg * 16 + c) * 8 + fp * 2];

    int warp  = (blockIdx.x * blockDim.x + threadIdx.x) >> 5;
    int nwarp = (gridDim.x * blockDim.x) >> 5;

    for (int n0 = warp * 2; n0 < N; n0 += nwarp * 2) {
        int n1 = n0 + 1;
        bool has1 = (n1 < N);

        const float4* xr0 = (const float4*)(x + (long long)n0 * 128);
        const float4* xr1 = (const float4*)(x + (long long)(has1 ? n1 : n0) * 128);

        float4 xa[4], xb[4];
#pragma unroll
        for (int i = 0; i < 4; i++) xa[i] = __ldcs(&xr0[cg * 4 + i]);
#pragma unroll
        for (int i = 0; i < 4; i++) xb[i] = __ldcs(&xr1[cg * 4 + i]);

        float a0 = 0.f, a1 = 0.f, b0 = 0.f, b1 = 0.f;
#pragma unroll
        for (int i = 0; i < 4; i++) {
            float2 wa = w2[i * 4 + 0], wb = w2[i * 4 + 1];
            float2 wc = w2[i * 4 + 2], wd = w2[i * 4 + 3];
            a0 = fmaf(xa[i].x, wa.x, a0); a1 = fmaf(xa[i].x, wa.y, a1);
            a0 = fmaf(xa[i].y, wb.x, a0); a1 = fmaf(xa[i].y, wb.y, a1);
            a0 = fmaf(xa[i].z, wc.x, a0); a1 = fmaf(xa[i].z, wc.y, a1);
            a0 = fmaf(xa[i].w, wd.x, a0); a1 = fmaf(xa[i].w, wd.y, a1);
            b0 = fmaf(xb[i].x, wa.x, b0); b1 = fmaf(xb[i].x, wa.y, b1);
            b0 = fmaf(xb[i].y, wb.x, b0); b1 = fmaf(xb[i].y, wb.y, b1);
            b0 = fmaf(xb[i].z, wc.x, b0); b1 = fmaf(xb[i].z, wc.y, b1);
            b0 = fmaf(xb[i].w, wd.x, b0); b1 = fmaf(xb[i].w, wd.y, b1);
        }
#pragma unroll
        for (int off = 16; off >= 4; off >>= 1) {
            a0 += __shfl_xor_sync(0xffffffffu, a0, off);
            a1 += __shfl_xor_sync(0xffffffffu, a1, off);
            b0 += __shfl_xor_sync(0xffffffffu, b0, off);
            b1 += __shfl_xor_sync(0xffffffffu, b1, off);
        }

        float r = 0.0f;
        if (lane < 2) {
            int nn = n0 + lane;
            if (nn < N) {
                r = rsqrtf(g_deg[nn]);
                g_dis[nn] = r;
            }
        }
        float r0 = __shfl_sync(0xffffffffu, r, 0);
        float r1 = __shfl_sync(0xffffffffu, r, 1);

        if (lane < 4) {
            float2 v0 = make_float2(a0 * r0, a1 * r0);
            *(float2*)&g_h[(long long)n0 * 8 + fp * 2]   = v0;
            *(float2*)&g_agg[(long long)n0 * 8 + fp * 2] = v0;
            if (has1) {
                float2 v1 = make_float2(b0 * r1, b1 * r1);
                *(float2*)&g_h[(long long)n1 * 8 + fp * 2]   = v1;
                *(float2*)&g_agg[(long long)n1 * 8 + fp * 2] = v1;
            }
        }
    }
}

// ---------------------------------------------------------------------------
__device__ __forceinline__ void red_v4(float* p, float4 v) {
    asm volatile("red.global.add.v4.f32 [%0], {%1, %2, %3, %4};"
                 :: "l"(p), "f"(v.x), "f"(v.y), "f"(v.z), "f"(v.w) : "memory");
}

// Unweighted 8-dim edge scatter, PAIR-COOPERATIVE (2 edges per lane pair):
// two adjacent lanes share each edge; each lane handles one 16B half of the
// 32B feature row, so the pair's gather (and RED) requests land in the SAME
// 32B sector and coalesce into one wavefront. Indices are read directly from
// edge_index; both pair lanes issue identical index loads which dedup.
__device__ __forceinline__ void scatter8(const void* __restrict__ ei, int E,
                                         const float* __restrict__ src_feat,
                                         float* __restrict__ dst_feat) {
    int t    = blockIdx.x * blockDim.x + threadIdx.x;
    int half = t & 1;            // which 16B half of the row
    int e0   = (t >> 1) * 2;     // first of 2 edges for this pair
    if (e0 >= E) return;

    int s0, d0, s1, d1;
    if (g_is64) {
        longlong2 sv = *(const longlong2*)((const long long*)ei + e0);
        longlong2 dv = *(const longlong2*)((const long long*)ei + E + e0);
        s0 = (int)sv.x; s1 = (int)sv.y;
        d0 = (int)dv.x; d1 = (int)dv.y;
    } else {
        int2 sv = *(const int2*)((const int*)ei + e0);
        int2 dv = *(const int2*)((const int*)ei + E + e0);
        s0 = sv.x; s1 = sv.y;
        d0 = dv.x; d1 = dv.y;
    }

    long long off = half * 4;
    float4 a = *(const float4*)(src_feat + (long long)s0 * 8 + off);
    bool h1 = (e0 + 1 < E);
    float4 b;
    if (h1) b = *(const float4*)(src_feat + (long long)s1 * 8 + off);

    red_v4(dst_feat + (long long)d0 * 8 + off, a);
    if (h1) red_v4(dst_feat + (long long)d1 * 8 + off, b);
}

__global__ void k_sc1(const void* ei, int E) { scatter8(ei, E, g_h, g_agg); }
__global__ void k_sc2(const void* ei, int E) { scatter8(ei, E, g_r, g_agg2); }

// ---------------------------------------------------------------------------
// K3: r = relu(agg * dis + b1) * dis; agg2 init = r.
__global__ void k_mid(const float* __restrict__ b1, int N) {
    __shared__ float sb1[8];
    if (threadIdx.x < 8) sb1[threadIdx.x] = b1[threadIdx.x];
    __syncthreads();

    int n = blockIdx.x * blockDim.x + threadIdx.x;
    if (n >= N) return;

    float dis = g_dis[n];
    const float4* ap = (const float4*)(g_agg + (long long)n * 8);
    float4 u = ap[0], v = ap[1];
    float4 r0 = make_float4(fmaxf(fmaf(u.x, dis, sb1[0]), 0.0f) * dis,
                            fmaxf(fmaf(u.y, dis, sb1[1]), 0.0f) * dis,
                            fmaxf(fmaf(u.z, dis, sb1[2]), 0.0f) * dis,
                            fmaxf(fmaf(u.w, dis, sb1[3]), 0.0f) * dis);
    float4 r1 = make_float4(fmaxf(fmaf(v.x, dis, sb1[4]), 0.0f) * dis,
                            fmaxf(fmaf(v.y, dis, sb1[5]), 0.0f) * dis,
                            fmaxf(fmaf(v.z, dis, sb1[6]), 0.0f) * dis,
                            fmaxf(fmaf(v.w, dis, sb1[7]), 0.0f) * dis);
    float4* rp = (float4*)(g_r + (long long)n * 8);
    float4* a2 = (float4*)(g_agg2 + (long long)n * 8);
    rp[0] = r0; rp[1] = r1;
    a2[0] = r0; a2[1] = r1;
}

// ---------------------------------------------------------------------------
// K4: out = (agg2 * dis) @ W2 + b2
__global__ void k_out(const float* __restrict__ W2, const float* __restrict__ b2,
                      float* __restrict__ out, int N) {
    __shared__ float sW[8 * 16];
    __shared__ float sb2[16];
    if (threadIdx.x < 128) sW[threadIdx.x] = W2[threadIdx.x];
    if (threadIdx.x < 16) sb2[threadIdx.x] = b2[threadIdx.x];
    __syncthreads();

    int n = blockIdx.x * blockDim.x + threadIdx.x;
    if (n >= N) return;

    float dis = g_dis[n];
    const float4* ap = (const float4*)(g_agg2 + (long long)n * 8);
    float4 u = ap[0], v = ap[1];
    float a[8] = {u.x * dis, u.y * dis, u.z * dis, u.w * dis,
                  v.x * dis, v.y * dis, v.z * dis, v.w * dis};

    float o[16];
#pragma unroll
    for (int j = 0; j < 16; j++) o[j] = sb2[j];
#pragma unroll
    for (int k = 0; k < 8; k++) {
        float ak = a[k];
#pragma unroll
        for (int j = 0; j < 16; j++) o[j] = fmaf(ak, sW[k * 16 + j], o[j]);
    }

    float4* op = (float4*)(out + (long long)n * 16);
#pragma unroll
    for (int q = 0; q < 4; q++)
        op[q] = make_float4(o[q * 4], o[q * 4 + 1], o[q * 4 + 2], o[q * 4 + 3]);
}

// ---------------------------------------------------------------------------
extern "C" void kernel_launch(void* const* d_in, const int* in_sizes, int n_in,
                              void* d_out, int out_size) {
    const float* x   = (const float*)d_in[0];
    const void*  ei  = d_in[1];
    const float* W1  = (const float*)d_in[2];
    const float* b1  = (const float*)d_in[3];
    const float* W2  = (const float*)d_in[4];
    const float* b2  = (const float*)d_in[5];
    float* out = (float*)d_out;

    int N = in_sizes[0] / 128;
    int E = in_sizes[1] / 2;

    const int T = 256;
    int nb_N  = (N + T - 1) / T;
    int nb_E8 = ((E + 7) / 8 + T - 1) / T;
    // scatter: 2 threads per 2 edges -> E threads total
    int nb_SC = (E + T - 1) / T;

    k_init<<<nb_N, T>>>(ei, N);
    k_deg<<<nb_E8, T>>>(ei, E);
    k_gemm1<<<1480, T>>>(x, W1, N);
    k_sc1<<<nb_SC, T>>>(ei, E);
    k_mid<<<nb_N, T>>>(b1, N);
    k_sc2<<<nb_SC, T>>>(ei, E);
    k_out<<<nb_N, T>>>(W2, b2, out, N);
}

// round 17
// speedup vs baseline: 1.0579x; 1.0579x over previous
#include <cuda_runtime.h>
#include <cstdint>

// Problem constants (fixed by the dataset): N=200000, E=6400000, F: 128 -> 8 -> 16
#define NMAX 200000
#define EMAX 6400000

// Scratch (no cudaMalloc allowed)
__device__ float g_deg[NMAX];         // degree (float counts)
__device__ float g_dis[NMAX];         // deg^-1/2
__device__ float g_h[NMAX * 8];       // (x @ W1) * dis[src]   (pre-scaled)
__device__ float g_agg[NMAX * 8];     // layer-1 unweighted aggregation
__device__ float g_r[NMAX * 8];       // relu(...) * dis[src]  (pre-scaled)
__device__ float g_agg2[NMAX * 8];    // layer-2 unweighted aggregation
__device__ int   g_is64;              // edge_index dtype flag

// ---------------------------------------------------------------------------
// K0: deg init + dtype detect (thread 0 of block 0).
__global__ void k_init(const void* ei, int N) {
    int i = blockIdx.x * blockDim.x + threadIdx.x;
    if (i < N) g_deg[i] = 1.0f;   // self-loop
    if (i == 0) {
        const long long* p = (const long long*)ei;
        int is64 = 1;
#pragma unroll
        for (int k = 0; k < 8; k++) {
            long long v = p[k];
            if (v < 0 || v >= (long long)N) is64 = 0;
        }
        g_is64 = is64;
    }
}

// ---------------------------------------------------------------------------
// K1: degree scatter only — streams the dst half of edge_index, 4 edges/thread.
__global__ void k_deg(const void* ei, int E) {
    int t = blockIdx.x * blockDim.x + threadIdx.x;
    int e = t * 4;
    if (e >= E) return;
    int d[4];
    if (g_is64) {
        longlong2 da = *(const longlong2*)((const long long*)ei + E + e);
        longlong2 db = *(const longlong2*)((const long long*)ei + E + e + 2);
        d[0] = (int)da.x; d[1] = (int)da.y; d[2] = (int)db.x; d[3] = (int)db.y;
    } else {
        int4 dv = *(const int4*)((const int*)ei + E + e);
        d[0] = dv.x; d[1] = dv.y; d[2] = dv.z; d[3] = dv.w;
    }
#pragma unroll
    for (int i = 0; i < 4; i++) atomicAdd(&g_deg[d[i]], 1.0f);
}

// ---------------------------------------------------------------------------
// Bulk-copy issue helper: expect_tx + cp.async.bulk (global->shared::cta).
__device__ __forceinline__ void issue_tile(unsigned int mb, unsigned int sxa,
                                           const float* src, unsigned int bytes) {
    asm volatile("mbarrier.arrive.expect_tx.shared.b64 _, [%0], %1;"
                 :: "r"(mb), "r"(bytes) : "memory");
    asm volatile("cp.async.bulk.shared::cluster.global"
                 ".mbarrier::complete_tx::bytes [%0], [%1], %2, [%3];"
                 :: "r"(sxa), "l"(src), "r"(bytes), "r"(mb) : "memory");
}

__device__ __forceinline__ void wait_tile(unsigned int mb, int phase) {
    asm volatile(
        "{\n\t.reg .pred P;\n\t"
        "WL%=:\n\t"
        "mbarrier.try_wait.parity.acquire.cta.shared::cta.b64 P, [%0], %1, 0x989680;\n\t"
        "@!P bra WL%=;\n\t}"
        :: "r"(mb), "r"(phase) : "memory");
}

// ---------------------------------------------------------------------------
// K2: h_scaled = (x @ W1) * dis, x staged through smem via cp.async.bulk.
// 32-row (16 KB) tiles, double-buffered, mbarrier expect_tx completion.
// Lane (cg, fp): at chunk-step i, lane reads smem float4 (cg + i*8) of its row
// -> 8 cg lanes cover one contiguous 128B, conflict-free; fp quad broadcasts.
// W register slice re-indexed to match: w2[i*4+k] = W1 row (i*32 + cg*4 + k).
// Fused: dis = rsqrt(deg) stored once, agg init = h_scaled (self-loop term).
#define TILE 32
__global__ void k_gemm1(const float* __restrict__ x, const float* __restrict__ W1, int N) {
    __shared__ float4 sx[2][TILE * 32];             // 2 x 16KB
    __shared__ unsigned long long mbar[2];

    int tid  = threadIdx.x;
    int lane = tid & 31;
    int wid  = tid >> 5;
    int cg   = lane >> 2;
    int fp   = lane & 3;

    float2 w2[16];
#pragma unroll
    for (int i = 0; i < 4; i++)
#pragma unroll
        for (int k = 0; k < 4; k++)
            w2[i * 4 + k] = *(const float2*)&W1[(i * 32 + cg * 4 + k) * 8 + fp * 2];

    unsigned int mb0  = (unsigned int)__cvta_generic_to_shared(&mbar[0]);
    unsigned int mb1  = (unsigned int)__cvta_generic_to_shared(&mbar[1]);
    unsigned int sxa0 = (unsigned int)__cvta_generic_to_shared(&sx[0][0]);
    unsigned int sxa1 = (unsigned int)__cvta_generic_to_shared(&sx[1][0]);

    if (tid == 0) {
        asm volatile("mbarrier.init.shared.b64 [%0], 1;" :: "r"(mb0) : "memory");
        asm volatile("mbarrier.init.shared.b64 [%0], 1;" :: "r"(mb1) : "memory");
        asm volatile("fence.proxy.async.shared::cta;" ::: "memory");
    }
    __syncthreads();

    int ntiles = (N + TILE - 1) / TILE;

    if (tid == 0 && (int)blockIdx.x < ntiles) {
        int t0 = blockIdx.x;
        int rows = N - t0 * TILE; if (rows > TILE) rows = TILE;
        issue_tile(mb0, sxa0, x + (long long)t0 * TILE * 128, (unsigned int)rows * 512u);
    }

    int ph0 = 0, ph1 = 0;
    int it = 0;
    for (int t = blockIdx.x; t < ntiles; t += gridDim.x, it++) {
        int slot = it & 1;
        int tn = t + gridDim.x;
        if (tid == 0 && tn < ntiles) {
            int rows = N - tn * TILE; if (rows > TILE) rows = TILE;
            issue_tile(slot ? mb0 : mb1, slot ? sxa0 : sxa1,
                       x + (long long)tn * TILE * 128, (unsigned int)rows * 512u);
        }

        if (slot) { wait_tile(mb1, ph1); ph1 ^= 1; }
        else      { wait_tile(mb0, ph0); ph0 ^= 1; }

        int base = t * TILE;
        const float4* sb = &sx[slot][0];
#pragma unroll
        for (int p = 0; p < 2; p++) {
            int r0 = wid * 4 + p * 2;
            int n0 = base + r0;
            if (n0 >= N) continue;
            int n1 = n0 + 1;
            bool has1 = (n1 < N);

            const float4* row0 = sb + r0 * 32;
            const float4* row1 = sb + (r0 + (has1 ? 1 : 0)) * 32;

            float a0 = 0.f, a1 = 0.f, b0 = 0.f, b1 = 0.f;
#pragma unroll
            for (int i = 0; i < 4; i++) {
                float4 xa = row0[cg + i * 8];
                float4 xb = row1[cg + i * 8];
                float2 wa = w2[i * 4 + 0], wb = w2[i * 4 + 1];
                float2 wc = w2[i * 4 + 2], wd = w2[i * 4 + 3];
                a0 = fmaf(xa.x, wa.x, a0); a1 = fmaf(xa.x, wa.y, a1);
                a0 = fmaf(xa.y, wb.x, a0); a1 = fmaf(xa.y, wb.y, a1);
                a0 = fmaf(xa.z, wc.x, a0); a1 = fmaf(xa.z, wc.y, a1);
                a0 = fmaf(xa.w, wd.x, a0); a1 = fmaf(xa.w, wd.y, a1);
                b0 = fmaf(xb.x, wa.x, b0); b1 = fmaf(xb.x, wa.y, b1);
                b0 = fmaf(xb.y, wb.x, b0); b1 = fmaf(xb.y, wb.y, b1);
                b0 = fmaf(xb.z, wc.x, b0); b1 = fmaf(xb.z, wc.y, b1);
                b0 = fmaf(xb.w, wd.x, b0); b1 = fmaf(xb.w, wd.y, b1);
            }
#pragma unroll
            for (int off = 16; off >= 4; off >>= 1) {
                a0 += __shfl_xor_sync(0xffffffffu, a0, off);
                a1 += __shfl_xor_sync(0xffffffffu, a1, off);
                b0 += __shfl_xor_sync(0xffffffffu, b0, off);
                b1 += __shfl_xor_sync(0xffffffffu, b1, off);
            }

            float r = 0.0f;
            if (lane < 2) {
                int nn = n0 + lane;
                if (nn < N) {
                    r = rsqrtf(g_deg[nn]);
                    g_dis[nn] = r;
                }
            }
            float r0f = __shfl_sync(0xffffffffu, r, 0);
            float r1f = __shfl_sync(0xffffffffu, r, 1);

            if (lane < 4) {
                float2 v0 = make_float2(a0 * r0f, a1 * r0f);
                *(float2*)&g_h[(long long)n0 * 8 + fp * 2]   = v0;
                *(float2*)&g_agg[(long long)n0 * 8 + fp * 2] = v0;
                if (has1) {
                    float2 v1 = make_float2(b0 * r1f, b1 * r1f);
                    *(float2*)&g_h[(long long)n1 * 8 + fp * 2]   = v1;
                    *(float2*)&g_agg[(long long)n1 * 8 + fp * 2] = v1;
                }
            }
        }
        __syncthreads();   // all warps done with this slot before it's refilled
    }
}

// ---------------------------------------------------------------------------
__device__ __forceinline__ void red_v4(float* p, float4 v) {
    asm volatile("red.global.add.v4.f32 [%0], {%1, %2, %3, %4};"
                 :: "l"(p), "f"(v.x), "f"(v.y), "f"(v.z), "f"(v.w) : "memory");
}

// Unweighted 8-dim edge scatter, PAIR-COOPERATIVE (2 edges per lane pair):
// two adjacent lanes share each edge; each lane handles one 16B half of the
// 32B feature row, so the pair's gather (and RED) requests land in the SAME
// 32B sector and coalesce into one wavefront. Indices read directly from
// edge_index; pair lanes issue identical index loads which dedup.
__device__ __forceinline__ void scatter8(const void* __restrict__ ei, int E,
                                         const float* __restrict__ src_feat,
                                         float* __restrict__ dst_feat) {
    int t    = blockIdx.x * blockDim.x + threadIdx.x;
    int half = t & 1;            // which 16B half of the row
    int e0   = (t >> 1) * 2;     // first of 2 edges for this pair
    if (e0 >= E) return;

    int s0, d0, s1, d1;
    if (g_is64) {
        longlong2 sv = *(const longlong2*)((const long long*)ei + e0);
        longlong2 dv = *(const longlong2*)((const long long*)ei + E + e0);
        s0 = (int)sv.x; s1 = (int)sv.y;
        d0 = (int)dv.x; d1 = (int)dv.y;
    } else {
        int2 sv = *(const int2*)((const int*)ei + e0);
        int2 dv = *(const int2*)((const int*)ei + E + e0);
        s0 = sv.x; s1 = sv.y;
        d0 = dv.x; d1 = dv.y;
    }

    long long off = half * 4;
    float4 a = *(const float4*)(src_feat + (long long)s0 * 8 + off);
    bool h1 = (e0 + 1 < E);
    float4 b;
    if (h1) b = *(const float4*)(src_feat + (long long)s1 * 8 + off);

    red_v4(dst_feat + (long long)d0 * 8 + off, a);
    if (h1) red_v4(dst_feat + (long long)d1 * 8 + off, b);
}

__global__ void k_sc1(const void* ei, int E) { scatter8(ei, E, g_h, g_agg); }
__global__ void k_sc2(const void* ei, int E) { scatter8(ei, E, g_r, g_agg2); }

// ---------------------------------------------------------------------------
// K3: r = relu(agg * dis + b1) * dis; agg2 init = r.
__global__ void k_mid(const float* __restrict__ b1, int N) {
    __shared__ float sb1[8];
    if (threadIdx.x < 8) sb1[threadIdx.x] = b1[threadIdx.x];
    __syncthreads();

    int n = blockIdx.x * blockDim.x + threadIdx.x;
    if (n >= N) return;

    float dis = g_dis[n];
    const float4* ap = (const float4*)(g_agg + (long long)n * 8);
    float4 u = ap[0], v = ap[1];
    float4 r0 = make_float4(fmaxf(fmaf(u.x, dis, sb1[0]), 0.0f) * dis,
                            fmaxf(fmaf(u.y, dis, sb1[1]), 0.0f) * dis,
                            fmaxf(fmaf(u.z, dis, sb1[2]), 0.0f) * dis,
                            fmaxf(fmaf(u.w, dis, sb1[3]), 0.0f) * dis);
    float4 r1 = make_float4(fmaxf(fmaf(v.x, dis, sb1[4]), 0.0f) * dis,
                            fmaxf(fmaf(v.y, dis, sb1[5]), 0.0f) * dis,
                            fmaxf(fmaf(v.z, dis, sb1[6]), 0.0f) * dis,
                            fmaxf(fmaf(v.w, dis, sb1[7]), 0.0f) * dis);
    float4* rp = (float4*)(g_r + (long long)n * 8);
    float4* a2 = (float4*)(g_agg2 + (long long)n * 8);
    rp[0] = r0; rp[1] = r1;
    a2[0] = r0; a2[1] = r1;
}

// ---------------------------------------------------------------------------
// K4: out = (agg2 * dis) @ W2 + b2
__global__ void k_out(const float* __restrict__ W2, const float* __restrict__ b2,
                      float* __restrict__ out, int N) {
    __shared__ float sW[8 * 16];
    __shared__ float sb2[16];
    if (threadIdx.x < 128) sW[threadIdx.x] = W2[threadIdx.x];
    if (threadIdx.x < 16) sb2[threadIdx.x] = b2[threadIdx.x];
    __syncthreads();

    int n = blockIdx.x * blockDim.x + threadIdx.x;
    if (n >= N) return;

    float dis = g_dis[n];
    const float4* ap = (const float4*)(g_agg2 + (long long)n * 8);
    float4 u = ap[0], v = ap[1];
    float a[8] = {u.x * dis, u.y * dis, u.z * dis, u.w * dis,
                  v.x * dis, v.y * dis, v.z * dis, v.w * dis};

    float o[16];
#pragma unroll
    for (int j = 0; j < 16; j++) o[j] = sb2[j];
#pragma unroll
    for (int k = 0; k < 8; k++) {
        float ak = a[k];
#pragma unroll
        for (int j = 0; j < 16; j++) o[j] = fmaf(ak, sW[k * 16 + j], o[j]);
    }

    float4* op = (float4*)(out + (long long)n * 16);
#pragma unroll
    for (int q = 0; q < 4; q++)
        op[q] = make_float4(o[q * 4], o[q * 4 + 1], o[q * 4 + 2], o[q * 4 + 3]);
}

// ---------------------------------------------------------------------------
extern "C" void kernel_launch(void* const* d_in, const int* in_sizes, int n_in,
                              void* d_out, int out_size) {
    const float* x   = (const float*)d_in[0];
    const void*  ei  = d_in[1];
    const float* W1  = (const float*)d_in[2];
    const float* b1  = (const float*)d_in[3];
    const float* W2  = (const float*)d_in[4];
    const float* b2  = (const float*)d_in[5];
    float* out = (float*)d_out;

    int N = in_sizes[0] / 128;
    int E = in_sizes[1] / 2;

    const int T = 256;
    int nb_N  = (N + T - 1) / T;
    int nb_E4 = ((E + 3) / 4 + T - 1) / T;
    // scatter: 2 threads per 2 edges -> E threads total
    int nb_SC = (E + T - 1) / T;

    k_init<<<nb_N, T>>>(ei, N);
    k_deg<<<nb_E4, T>>>(ei, E);
    k_gemm1<<<888, T>>>(x, W1, N);
    k_sc1<<<nb_SC, T>>>(ei, E);
    k_mid<<<nb_N, T>>>(b1, N);
    k_sc2<<<nb_SC, T>>>(ei, E);
    k_out<<<nb_N, T>>>(W2, b2, out, N);
}